// round 5
// baseline (speedup 1.0000x reference)
#include <cuda_runtime.h>
#include <cstdint>
#include <math.h>

// ---------------- problem constants ----------------
#define BTC   192
#define NQC   64
#define NCC   1024
#define CCD   384
#define HCN   8
#define DHC   48
#define HIDC  1536
#define MROWS (BTC*NQC)     // 12288
#define CROWS (BTC*NCC)     // 196608

// ---------------- scratch (device globals; no allocs allowed) ----------------
__device__ float g_xn [MROWS*CCD];
__device__ float g_cn [(size_t)CROWS*CCD];
__device__ float g_q  [MROWS*CCD];
__device__ float g_kv [(size_t)CROWS*2*CCD];
__device__ float g_ob [MROWS*CCD];
__device__ float g_x1 [MROWS*CCD];
__device__ float g_h  [MROWS*HIDC];
__device__ float g_mk [MROWS];
__device__ float g_wt [1769472];   // transposed weights

// ---------------- small helpers ----------------
__device__ __forceinline__ float to_tf32(float x){
    uint32_t u; asm("cvt.rna.tf32.f32 %0, %1;" : "=r"(u) : "f"(x));
    return __uint_as_float(u);
}
__device__ __forceinline__ uint32_t smem_u32(const void* p){
    uint32_t a;
    asm("{ .reg .u64 t; cvta.to.shared.u64 t, %1; cvt.u32.u64 %0, t; }" : "=r"(a) : "l"(p));
    return a;
}
__device__ __forceinline__ void cp16(uint32_t dst, const void* src){
    asm volatile("cp.async.cg.shared.global [%0], [%1], 16;" :: "r"(dst), "l"(src) : "memory");
}
__device__ __forceinline__ float gelu_tanh(float x){
    float x3 = x*x*x;
    return 0.5f*x*(1.0f + tanhf(0.7978845608028654f*(x + 0.044715f*x3)));
}
__device__ __forceinline__ void mma8(float* c, float a0,float a1,float a2,float a3,
                                     float b0,float b1){
    asm volatile("mma.sync.aligned.m16n8k8.row.col.f32.tf32.tf32.f32 "
        "{%0,%1,%2,%3}, {%4,%5,%6,%7}, {%8,%9}, {%0,%1,%2,%3};\n"
        : "+f"(c[0]), "+f"(c[1]), "+f"(c[2]), "+f"(c[3])
        : "r"(__float_as_uint(a0)), "r"(__float_as_uint(a1)),
          "r"(__float_as_uint(a2)), "r"(__float_as_uint(a3)),
          "r"(__float_as_uint(b0)), "r"(__float_as_uint(b1)));
}

// ---------------- multistage cp.async tf32 GEMM (swizzled, conflict-free) ----
// C = A(MxK, tf32-rounded) @ BT(NxK, tf32-rounded)^T + bias
// EPI 0: bias; 1: bias+residual; 2: bias+gelu (tf32-rounded out).
// Tile: 128x128 CTA, K=32 per stage, 3 stages, 4 warps of 64x64.
// smem tile layout (per operand): 128 rows x 128B; 16B chunk c of row r at
// byte offset r*128 + ((c ^ (r&7))<<4). Element (r,k) at float index
// r*32 + (((k>>2) ^ (r&7))<<2) + (k&3).
#define STAGES    3
#define TILE_B    16384u                       // bytes per operand tile
#define STAGE_B   (2u*TILE_B)                  // A + B
#define GEMM_SMEM (STAGES*STAGE_B)             // 98304 bytes

template<int EPI>
__global__ void __launch_bounds__(128, 2) gemm_cp(
        const float* __restrict__ A, const float* __restrict__ BT,
        const float* __restrict__ bias, const float* __restrict__ R,
        float* __restrict__ C_, int M, int N, int K){
    extern __shared__ float sm[];
    const int tid = threadIdx.x, lane = tid & 31, wid = tid >> 5;
    const int l4 = lane & 3, ld4 = lane >> 2;
    const int m0 = blockIdx.y * 128, n0 = blockIdx.x * 128;
    const int wm = wid >> 1, wn = wid & 1;

    const uint32_t sbase = smem_u32(sm);
    const float* Ag = A  + (size_t)(m0 + tid)*K;
    const float* Bg = BT + (size_t)(n0 + tid)*K;
    const uint32_t rowoff = (uint32_t)tid * 128u;
    const int t7 = tid & 7;

    float acc[4][8][4];
#pragma unroll
    for (int mt=0;mt<4;mt++)
#pragma unroll
        for (int ni=0;ni<8;ni++)
#pragma unroll
            for (int j=0;j<4;j++) acc[mt][ni][j] = 0.f;

    const int nk = K >> 5;      // K=384 -> 12, K=1536 -> 48

    // prologue: tiles 0,1 -> slots 0,1
#pragma unroll
    for (int s=0; s<STAGES-1; s++){
        const uint32_t ab = sbase + (uint32_t)s*STAGE_B + rowoff;
        const uint32_t bb = ab + TILE_B;
        const float* ag = Ag + s*32;
        const float* bg = Bg + s*32;
#pragma unroll
        for (int c=0;c<8;c++){
            const uint32_t d = (uint32_t)((c ^ t7) << 4);
            cp16(ab + d, ag + c*4);
            cp16(bb + d, bg + c*4);
        }
        asm volatile("cp.async.commit_group;" ::: "memory");
    }

    int sl = STAGES-1, sc = 0;
    for (int kt = 0; kt < nk; kt++){
        asm volatile("cp.async.wait_group %0;" :: "n"(STAGES-2) : "memory");
        __syncthreads();

        // issue tile kt+2 into slot sl (the slot computed last iteration)
        if (kt + STAGES-1 < nk){
            const uint32_t ab = sbase + (uint32_t)sl*STAGE_B + rowoff;
            const uint32_t bb = ab + TILE_B;
            const float* ag = Ag + (kt+STAGES-1)*32;
            const float* bg = Bg + (kt+STAGES-1)*32;
#pragma unroll
            for (int c=0;c<8;c++){
                const uint32_t d = (uint32_t)((c ^ t7) << 4);
                cp16(ab + d, ag + c*4);
                cp16(bb + d, bg + c*4);
            }
        }
        asm volatile("cp.async.commit_group;" ::: "memory");
        sl = (sl + 1 == STAGES) ? 0 : sl + 1;

        const float* Asb = sm + sc*(STAGE_B/4);
        const float* Bsb = Asb + TILE_B/4;
        sc = (sc + 1 == STAGES) ? 0 : sc + 1;

#pragma unroll
        for (int ks=0; ks<4; ks++){
            const int xo0 = (((2*ks  ) ^ ld4) << 2) + l4;
            const int xo1 = (((2*ks+1) ^ ld4) << 2) + l4;
            float a[4][4]; float b[8][2];
#pragma unroll
            for (int mt=0;mt<4;mt++){
                const int r1 = (wm*64 + mt*16 + ld4)*32;
                const int r2 = r1 + 8*32;
                a[mt][0] = Asb[r1 + xo0];
                a[mt][1] = Asb[r2 + xo0];
                a[mt][2] = Asb[r1 + xo1];
                a[mt][3] = Asb[r2 + xo1];
            }
#pragma unroll
            for (int ni=0;ni<8;ni++){
                const int nn = (wn*64 + ni*8 + ld4)*32;
                b[ni][0] = Bsb[nn + xo0];
                b[ni][1] = Bsb[nn + xo1];
            }
#pragma unroll
            for (int mt=0;mt<4;mt++)
#pragma unroll
                for (int ni=0;ni<8;ni++)
                    mma8(acc[mt][ni], a[mt][0],a[mt][1],a[mt][2],a[mt][3],
                         b[ni][0], b[ni][1]);
        }
    }

    // epilogue
#pragma unroll
    for (int mt=0;mt<4;mt++){
        const int row = m0 + wm*64 + mt*16 + ld4;
#pragma unroll
        for (int ni=0;ni<8;ni++){
            const int col = n0 + wn*64 + ni*8 + 2*l4;
            float b0v = bias[col], b1v = bias[col+1];
            float v0 = acc[mt][ni][0] + b0v, v1 = acc[mt][ni][1] + b1v;
            float v2 = acc[mt][ni][2] + b0v, v3 = acc[mt][ni][3] + b1v;
            if (EPI == 1){
                float2 r0 = *(const float2*)(R + (size_t)row*N + col);
                float2 r1 = *(const float2*)(R + (size_t)(row+8)*N + col);
                v0 += r0.x; v1 += r0.y; v2 += r1.x; v3 += r1.y;
            }
            if (EPI == 2){
                v0 = to_tf32(gelu_tanh(v0)); v1 = to_tf32(gelu_tanh(v1));
                v2 = to_tf32(gelu_tanh(v2)); v3 = to_tf32(gelu_tanh(v3));
            }
            float2 w0; w0.x = v0; w0.y = v1;
            float2 w1; w1.x = v2; w1.y = v3;
            *(float2*)(C_ + (size_t)row*N + col)     = w0;
            *(float2*)(C_ + (size_t)(row+8)*N + col) = w1;
        }
    }
}

// ---------------- weight transpose (tf32-rounded): WT[n][k] = W[k][n] ----------------
__global__ void transpose_kernel(const float* __restrict__ W, float* __restrict__ WT,
                                 int K, int N){
    __shared__ float t[32][33];
    int n0 = blockIdx.x*32, k0 = blockIdx.y*32;
    int tx = threadIdx.x, ty = threadIdx.y;     // 32 x 8
#pragma unroll
    for (int i=0;i<32;i+=8)
        t[ty+i][tx] = W[(size_t)(k0+ty+i)*N + n0+tx];
    __syncthreads();
#pragma unroll
    for (int i=0;i<32;i+=8)
        WT[(size_t)(n0+ty+i)*K + k0+tx] = to_tf32(t[tx][ty+i]);
}

// ---------------- LayerNorm (tf32-rounded output): one warp per row of 384 ----------------
__global__ void __launch_bounds__(256) ln_kernel(const float* __restrict__ in,
        float* __restrict__ out, const float* __restrict__ g,
        const float* __restrict__ b, float eps){
    int warp = threadIdx.x >> 5, lane = threadIdx.x & 31;
    int row  = blockIdx.x * 8 + warp;
    const float4* ip = (const float4*)(in + (size_t)row*CCD);
    float4 v[3];
    float s = 0.f, ss = 0.f;
#pragma unroll
    for (int j=0;j<3;j++){
        v[j] = ip[lane + j*32];
        s  += v[j].x + v[j].y + v[j].z + v[j].w;
        ss += v[j].x*v[j].x + v[j].y*v[j].y + v[j].z*v[j].z + v[j].w*v[j].w;
    }
#pragma unroll
    for (int o=16;o;o>>=1){
        s  += __shfl_xor_sync(0xffffffffu, s,  o);
        ss += __shfl_xor_sync(0xffffffffu, ss, o);
    }
    float mean = s * (1.f/CCD);
    float var  = ss * (1.f/CCD) - mean*mean;
    float r    = rsqrtf(var + eps);
    float4* op = (float4*)(out + (size_t)row*CCD);
    if (g){
#pragma unroll
        for (int j=0;j<3;j++){
            float4 gg = ((const float4*)g)[lane + j*32];
            float4 bb = ((const float4*)b)[lane + j*32];
            float4 y;
            y.x = to_tf32((v[j].x-mean)*r*gg.x + bb.x);
            y.y = to_tf32((v[j].y-mean)*r*gg.y + bb.y);
            y.z = to_tf32((v[j].z-mean)*r*gg.z + bb.z);
            y.w = to_tf32((v[j].w-mean)*r*gg.w + bb.w);
            op[lane + j*32] = y;
        }
    } else {
#pragma unroll
        for (int j=0;j<3;j++){
            float4 y;
            y.x = to_tf32((v[j].x-mean)*r); y.y = to_tf32((v[j].y-mean)*r);
            y.z = to_tf32((v[j].z-mean)*r); y.w = to_tf32((v[j].w-mean)*r);
            op[lane + j*32] = y;
        }
    }
}

// ---------------- mask dtype classification + conversion ----------------
__global__ void mask_conv(const unsigned char* __restrict__ m, float* __restrict__ out){
    __shared__ int cls1, cls3;
    if (threadIdx.x == 0){ cls1 = 0; cls3 = 0; }
    __syncthreads();
    int a1 = 0, a3 = 0;
    for (int i = threadIdx.x; i < MROWS; i += blockDim.x){
        if (m[i]){
            int ph = i & 3;
            if (ph == 1) a1 = 1;
            if (ph == 3) a3 = 1;
        }
    }
    if (a1) atomicOr(&cls1, 1);
    if (a3) atomicOr(&cls3, 1);
    __syncthreads();
    bool isb8  = (cls1 != 0);
    bool isf32 = (!isb8) && (cls3 != 0);
    for (int i = threadIdx.x; i < MROWS; i += blockDim.x){
        float v;
        if (isb8)       v = m[i] ? 1.f : 0.f;
        else if (isf32) v = (((const float*)m)[i] != 0.f) ? 1.f : 0.f;
        else            v = (((const int*)m)[i]   != 0  ) ? 1.f : 0.f;
        out[i] = v;
    }
}

// ---------------- fused attention (O output tf32-rounded) ----------------
#define ATTN_SMEM_FLOATS (64*52 + 128*52 + 128*56 + 64*132 + 4*64)

__global__ void __launch_bounds__(256) attn_kernel(const float* __restrict__ Q,
        const float* __restrict__ KV, const float* __restrict__ maskf,
        float* __restrict__ O){
    extern __shared__ float smn[];
    float (*Qs)[52]  = (float(*)[52]) (smn);
    float (*Ks)[52]  = (float(*)[52]) (smn + 64*52);
    float (*Vs)[56]  = (float(*)[56]) (smn + 64*52 + 128*52);
    float (*Ss)[132] = (float(*)[132])(smn + 64*52 + 128*52 + 128*56);
    float* m_s  = smn + 64*52 + 128*52 + 128*56 + 64*132;
    float* l_s  = m_s  + 64;
    float* sc_s = l_s  + 64;
    float* mk_s = sc_s + 64;

    const int b = blockIdx.y, h = blockIdx.x;
    const int tid = threadIdx.x, lane = tid & 31, wid = tid >> 5;
    const int l4 = lane & 3, ld4 = lane >> 2;
    const int wm = wid >> 1, wn = wid & 1;
    const int mr = wm*16 + ld4;
    const int srow = tid >> 2, sub = tid & 3;

    const float* qh = Q  + ((size_t)b*NQC)*CCD + h*DHC;
    const float* kh = KV + ((size_t)b*NCC)*(2*CCD) + h*DHC;
    const float* vh = kh + CCD;
    const float scale = 0.14433756729740643f;

    for (int i = tid; i < 64*48; i += 256){
        int r = i/48, c = i - r*48;
        Qs[r][c] = to_tf32(qh[(size_t)r*CCD + c] * scale);
    }
    if (tid < 64){
        m_s[tid] = -1e30f; l_s[tid] = 0.f;
        mk_s[tid] = maskf[b*NQC + tid];
    }
    float oacc[3][4];
#pragma unroll
    for (int ni=0;ni<3;ni++)
#pragma unroll
        for (int j=0;j<4;j++) oacc[ni][j] = 0.f;
    __syncthreads();

    for (int c0 = 0; c0 < NCC; c0 += 128){
        for (int i = tid; i < 128*48; i += 256){
            int r = i/48, c = i - r*48;
            Ks[r][c] = to_tf32(kh[(size_t)(c0+r)*(2*CCD) + c]);
            Vs[r][c] = to_tf32(vh[(size_t)(c0+r)*(2*CCD) + c]);
        }
        __syncthreads();

        float sacc[8][4];
#pragma unroll
        for (int ni=0;ni<8;ni++){ sacc[ni][0]=sacc[ni][1]=sacc[ni][2]=sacc[ni][3]=0.f; }
#pragma unroll
        for (int k=0;k<48;k+=8){
            float a0=Qs[mr][k+l4], a1=Qs[mr+8][k+l4];
            float a2=Qs[mr][k+l4+4], a3=Qs[mr+8][k+l4+4];
#pragma unroll
            for (int ni=0;ni<8;ni++){
                int nn = wn*64 + ni*8 + ld4;
                mma8(sacc[ni], a0,a1,a2,a3, Ks[nn][k+l4], Ks[nn][k+l4+4]);
            }
        }
#pragma unroll
        for (int ni=0;ni<8;ni++){
            int cc = wn*64 + ni*8 + 2*l4;
            Ss[mr  ][cc] = sacc[ni][0]; Ss[mr  ][cc+1] = sacc[ni][1];
            Ss[mr+8][cc] = sacc[ni][2]; Ss[mr+8][cc+1] = sacc[ni][3];
        }
        __syncthreads();

        {
            float keep = mk_s[srow];
            float mold = m_s[srow];
            float mx = -1e30f;
#pragma unroll 8
            for (int j=0;j<32;j++){
                float s = Ss[srow][sub*32 + j] * keep;
                mx = fmaxf(mx, s);
            }
            mx = fmaxf(mx, __shfl_xor_sync(0xffffffffu, mx, 1));
            mx = fmaxf(mx, __shfl_xor_sync(0xffffffffu, mx, 2));
            float mnew = fmaxf(mold, mx);
            float lsum = 0.f;
#pragma unroll 8
            for (int j=0;j<32;j++){
                int cc = sub*32 + j;
                float s = Ss[srow][cc] * keep;
                float p = __expf(s - mnew);
                lsum += p;
                Ss[srow][cc] = to_tf32(p);
            }
            lsum += __shfl_xor_sync(0xffffffffu, lsum, 1);
            lsum += __shfl_xor_sync(0xffffffffu, lsum, 2);
            if (sub == 0){
                float scl = __expf(mold - mnew);
                m_s[srow] = mnew;
                l_s[srow] = l_s[srow]*scl + lsum;
                sc_s[srow] = scl;
            }
        }
        __syncthreads();

        {
            float s0 = sc_s[mr], s1 = sc_s[mr+8];
#pragma unroll
            for (int ni=0;ni<3;ni++){
                oacc[ni][0]*=s0; oacc[ni][1]*=s0; oacc[ni][2]*=s1; oacc[ni][3]*=s1;
            }
#pragma unroll
            for (int k=0;k<128;k+=8){
                float a0=Ss[mr][k+l4], a1=Ss[mr+8][k+l4];
                float a2=Ss[mr][k+l4+4], a3=Ss[mr+8][k+l4+4];
#pragma unroll
                for (int ni=0;ni<3;ni++){
                    int nn = wn*24 + ni*8 + ld4;
                    mma8(oacc[ni], a0,a1,a2,a3, Vs[k+l4][nn], Vs[k+l4+4][nn]);
                }
            }
        }
        __syncthreads();
    }

    float inv0 = 1.f / l_s[mr];
    float inv1 = 1.f / l_s[mr+8];
#pragma unroll
    for (int ni=0;ni<3;ni++){
        int cc = wn*24 + ni*8 + 2*l4;
        size_t b0 = ((size_t)b*NQC + mr  )*CCD + h*DHC + cc;
        size_t b1 = ((size_t)b*NQC + mr+8)*CCD + h*DHC + cc;
        O[b0] = to_tf32(oacc[ni][0]*inv0); O[b0+1] = to_tf32(oacc[ni][1]*inv0);
        O[b1] = to_tf32(oacc[ni][2]*inv1); O[b1+1] = to_tf32(oacc[ni][3]*inv1);
    }
}

// ---------------- launcher ----------------
static float* sym_addr(const void* sym){
    void* p = nullptr;
    cudaGetSymbolAddress(&p, sym);
    return (float*)p;
}

extern "C" void kernel_launch(void* const* d_in, const int* in_sizes, int n_in,
                              void* d_out, int out_size){
    const float* x    = (const float*)d_in[0];
    const float* ctx  = (const float*)d_in[1];
    const unsigned char* mask = (const unsigned char*)d_in[2];
    const float* Wq   = (const float*)d_in[3];
    const float* bq   = (const float*)d_in[4];
    const float* Wkv  = (const float*)d_in[5];
    const float* bkv  = (const float*)d_in[6];
    const float* Wo   = (const float*)d_in[7];
    const float* bo   = (const float*)d_in[8];
    const float* gctx = (const float*)d_in[9];
    const float* bctx = (const float*)d_in[10];
    const float* W1   = (const float*)d_in[11];
    const float* b1   = (const float*)d_in[12];
    const float* W2   = (const float*)d_in[13];
    const float* b2   = (const float*)d_in[14];
    float* out = (float*)d_out;

    float* xn = sym_addr(g_xn);
    float* cn = sym_addr(g_cn);
    float* qb = sym_addr(g_q);
    float* kv = sym_addr(g_kv);
    float* ob = sym_addr(g_ob);
    float* x1 = sym_addr(g_x1);
    float* hb = sym_addr(g_h);
    float* mk = sym_addr(g_mk);
    float* wt = sym_addr(g_wt);

    float* WqT  = wt;                      // 384x384
    float* WkvT = wt + 147456;             // 768x384
    float* WoT  = wt + 442368;             // 384x384
    float* W1T  = wt + 589824;             // 1536x384
    float* W2T  = wt + 1179648;            // 384x1536

    const int smem_attn = ATTN_SMEM_FLOATS * 4;
    cudaFuncSetAttribute(attn_kernel, cudaFuncAttributeMaxDynamicSharedMemorySize, smem_attn);
    cudaFuncSetAttribute(gemm_cp<0>, cudaFuncAttributeMaxDynamicSharedMemorySize, GEMM_SMEM);
    cudaFuncSetAttribute(gemm_cp<1>, cudaFuncAttributeMaxDynamicSharedMemorySize, GEMM_SMEM);
    cudaFuncSetAttribute(gemm_cp<2>, cudaFuncAttributeMaxDynamicSharedMemorySize, GEMM_SMEM);

    dim3 tb(32, 8);
    transpose_kernel<<<dim3(CCD/32,  CCD/32 ), tb>>>(Wq,  WqT,  CCD,  CCD);
    transpose_kernel<<<dim3(2*CCD/32,CCD/32 ), tb>>>(Wkv, WkvT, CCD,  2*CCD);
    transpose_kernel<<<dim3(CCD/32,  CCD/32 ), tb>>>(Wo,  WoT,  CCD,  CCD);
    transpose_kernel<<<dim3(HIDC/32, CCD/32 ), tb>>>(W1,  W1T,  CCD,  HIDC);
    transpose_kernel<<<dim3(CCD/32,  HIDC/32), tb>>>(W2,  W2T,  HIDC, CCD);

    // 1. LN(x), LN(context), mask conversion
    ln_kernel<<<MROWS/8, 256>>>(x, xn, nullptr, nullptr, 1e-6f);
    ln_kernel<<<CROWS/8, 256>>>(ctx, cn, gctx, bctx, 1e-5f);
    mask_conv<<<1, 256>>>(mask, mk);

    // 2. q = xn@Wq + bq ; kv = cn@Wkv + bkv
    gemm_cp<0><<<dim3(CCD/128,   MROWS/128), 128, GEMM_SMEM>>>(xn, WqT,  bq,  nullptr, qb, MROWS, CCD,   CCD);
    gemm_cp<0><<<dim3(2*CCD/128, CROWS/128), 128, GEMM_SMEM>>>(cn, WkvT, bkv, nullptr, kv, CROWS, 2*CCD, CCD);

    // 3. attention
    attn_kernel<<<dim3(HCN, BTC), 256, smem_attn>>>(qb, kv, mk, ob);

    // 4. x1 = x + o@Wo + bo
    gemm_cp<1><<<dim3(CCD/128, MROWS/128), 128, GEMM_SMEM>>>(ob, WoT, bo, x, x1, MROWS, CCD, CCD);

    // 5. MLP: out = x1 + gelu(LN(x1)@W1+b1)@W2 + b2
    ln_kernel<<<MROWS/8, 256>>>(x1, xn, nullptr, nullptr, 1e-6f);
    gemm_cp<2><<<dim3(HIDC/128, MROWS/128), 128, GEMM_SMEM>>>(xn, W1T, b1, nullptr, hb, MROWS, HIDC, CCD);
    gemm_cp<1><<<dim3(CCD/128,  MROWS/128), 128, GEMM_SMEM>>>(hb, W2T, b2, x1, out, MROWS, CCD, HIDC);
}

// round 6
// speedup vs baseline: 1.5401x; 1.5401x over previous
#include <cuda_runtime.h>
#include <cstdint>
#include <math.h>

// ---------------- problem constants ----------------
#define BTC   192
#define NQC   64
#define NCC   1024
#define CCD   384
#define HCN   8
#define DHC   48
#define HIDC  1536
#define MROWS (BTC*NQC)     // 12288
#define CROWS (BTC*NCC)     // 196608

// ---------------- scratch (device globals; no allocs allowed) ----------------
__device__ float g_xn [MROWS*CCD];
__device__ float g_cn [(size_t)CROWS*CCD];
__device__ float g_q  [MROWS*CCD];
__device__ float g_kv [(size_t)CROWS*2*CCD];
__device__ float g_ob [MROWS*CCD];
__device__ float g_x1 [MROWS*CCD];
__device__ float g_h  [MROWS*HIDC];
__device__ float g_mk [MROWS];
__device__ float g_wt [1769472];   // transposed weights

// ---------------- small helpers ----------------
__device__ __forceinline__ float to_tf32(float x){
    uint32_t u; asm("cvt.rna.tf32.f32 %0, %1;" : "=r"(u) : "f"(x));
    return __uint_as_float(u);
}
__device__ __forceinline__ uint32_t smem_u32(const void* p){
    uint32_t a;
    asm("{ .reg .u64 t; cvta.to.shared.u64 t, %1; cvt.u32.u64 %0, t; }" : "=r"(a) : "l"(p));
    return a;
}
__device__ __forceinline__ void cp16(uint32_t dst, const void* src){
    asm volatile("cp.async.cg.shared.global [%0], [%1], 16;" :: "r"(dst), "l"(src) : "memory");
}
__device__ __forceinline__ float gelu_tanh(float x){
    float x3 = x*x*x;
    return 0.5f*x*(1.0f + tanhf(0.7978845608028654f*(x + 0.044715f*x3)));
}
__device__ __forceinline__ void mma8(float* c, float a0,float a1,float a2,float a3,
                                     float b0,float b1){
    asm volatile("mma.sync.aligned.m16n8k8.row.col.f32.tf32.tf32.f32 "
        "{%0,%1,%2,%3}, {%4,%5,%6,%7}, {%8,%9}, {%0,%1,%2,%3};\n"
        : "+f"(c[0]), "+f"(c[1]), "+f"(c[2]), "+f"(c[3])
        : "r"(__float_as_uint(a0)), "r"(__float_as_uint(a1)),
          "r"(__float_as_uint(a2)), "r"(__float_as_uint(a3)),
          "r"(__float_as_uint(b0)), "r"(__float_as_uint(b1)));
}

// ---------------- multistage cp.async tf32 GEMM (coalesced fill) -------------
// C = A(MxK, tf32-rounded) @ BT(NxK, tf32-rounded)^T + bias
// EPI 0: bias; 1: bias+residual; 2: bias+gelu (tf32-rounded out).
// Tile: 128x128 CTA, K=32 per stage, 3 stages, 4 warps of 64x64.
// Fill mapping: 8 threads per row (tid&7 = 16B chunk, tid>>3 = row, +16g).
// Per warp instruction: 4 complete 128B rows -> nL=4, no sector waste.
// smem: 16B chunk c of row r at byte r*128 + ((c ^ (r&7))<<4); element (r,k)
// at float index r*32 + (((k>>2) ^ (r&7))<<2) + (k&3).  Conflict-free fill+drain.
#define STAGES    3
#define TILE_B    16384u
#define STAGE_B   (2u*TILE_B)
#define GEMM_SMEM (STAGES*STAGE_B)             // 98304 bytes

template<int EPI>
__global__ void __launch_bounds__(128, 2) gemm_cp(
        const float* __restrict__ A, const float* __restrict__ BT,
        const float* __restrict__ bias, const float* __restrict__ R,
        float* __restrict__ C_, int M, int N, int K){
    extern __shared__ float sm[];
    const int tid = threadIdx.x, lane = tid & 31, wid = tid >> 5;
    const int l4 = lane & 3, ld4 = lane >> 2;
    const int m0 = blockIdx.y * 128, n0 = blockIdx.x * 128;
    const int wm = wid >> 1, wn = wid & 1;

    const uint32_t sbase = smem_u32(sm);
    // fill mapping: 8 threads/row
    const int frow = tid >> 3;          // 0..15
    const int fchk = tid & 7;           // 16B chunk within K=32
    const float* Ag = A  + (size_t)(m0 + frow)*K + fchk*4;
    const float* Bg = BT + (size_t)(n0 + frow)*K + fchk*4;
    const uint32_t rowbase = (uint32_t)frow*128u + (uint32_t)((fchk ^ (frow & 7)) << 4);

    float acc[4][8][4];
#pragma unroll
    for (int mt=0;mt<4;mt++)
#pragma unroll
        for (int ni=0;ni<8;ni++)
#pragma unroll
            for (int j=0;j<4;j++) acc[mt][ni][j] = 0.f;

    const int nk = K >> 5;      // K=384 -> 12, K=1536 -> 48

    // prologue: tiles 0,1 -> slots 0,1
#pragma unroll
    for (int s=0; s<STAGES-1; s++){
        const uint32_t ab = sbase + (uint32_t)s*STAGE_B + rowbase;
        const uint32_t bb = ab + TILE_B;
        const float* ag = Ag + s*32;
        const float* bg = Bg + s*32;
#pragma unroll
        for (int g=0;g<8;g++){
            cp16(ab + g*2048u, ag + (size_t)(16*g)*K);
            cp16(bb + g*2048u, bg + (size_t)(16*g)*K);
        }
        asm volatile("cp.async.commit_group;" ::: "memory");
    }

    int sl = STAGES-1, sc = 0;
    for (int kt = 0; kt < nk; kt++){
        asm volatile("cp.async.wait_group %0;" :: "n"(STAGES-2) : "memory");
        __syncthreads();

        if (kt + STAGES-1 < nk){
            const uint32_t ab = sbase + (uint32_t)sl*STAGE_B + rowbase;
            const uint32_t bb = ab + TILE_B;
            const float* ag = Ag + (kt+STAGES-1)*32;
            const float* bg = Bg + (kt+STAGES-1)*32;
#pragma unroll
            for (int g=0;g<8;g++){
                cp16(ab + g*2048u, ag + (size_t)(16*g)*K);
                cp16(bb + g*2048u, bg + (size_t)(16*g)*K);
            }
        }
        asm volatile("cp.async.commit_group;" ::: "memory");
        sl = (sl + 1 == STAGES) ? 0 : sl + 1;

        const float* Asb = sm + sc*(STAGE_B/4);
        const float* Bsb = Asb + TILE_B/4;
        sc = (sc + 1 == STAGES) ? 0 : sc + 1;

#pragma unroll
        for (int ks=0; ks<4; ks++){
            const int xo0 = (((2*ks  ) ^ ld4) << 2) + l4;
            const int xo1 = (((2*ks+1) ^ ld4) << 2) + l4;
            float a[4][4]; float b[8][2];
#pragma unroll
            for (int mt=0;mt<4;mt++){
                const int r1 = (wm*64 + mt*16 + ld4)*32;
                const int r2 = r1 + 8*32;
                a[mt][0] = Asb[r1 + xo0];
                a[mt][1] = Asb[r2 + xo0];
                a[mt][2] = Asb[r1 + xo1];
                a[mt][3] = Asb[r2 + xo1];
            }
#pragma unroll
            for (int ni=0;ni<8;ni++){
                const int nn = (wn*64 + ni*8 + ld4)*32;
                b[ni][0] = Bsb[nn + xo0];
                b[ni][1] = Bsb[nn + xo1];
            }
#pragma unroll
            for (int mt=0;mt<4;mt++)
#pragma unroll
                for (int ni=0;ni<8;ni++)
                    mma8(acc[mt][ni], a[mt][0],a[mt][1],a[mt][2],a[mt][3],
                         b[ni][0], b[ni][1]);
        }
    }

    // epilogue
#pragma unroll
    for (int mt=0;mt<4;mt++){
        const int row = m0 + wm*64 + mt*16 + ld4;
#pragma unroll
        for (int ni=0;ni<8;ni++){
            const int col = n0 + wn*64 + ni*8 + 2*l4;
            float b0v = bias[col], b1v = bias[col+1];
            float v0 = acc[mt][ni][0] + b0v, v1 = acc[mt][ni][1] + b1v;
            float v2 = acc[mt][ni][2] + b0v, v3 = acc[mt][ni][3] + b1v;
            if (EPI == 1){
                float2 r0 = *(const float2*)(R + (size_t)row*N + col);
                float2 r1 = *(const float2*)(R + (size_t)(row+8)*N + col);
                v0 += r0.x; v1 += r0.y; v2 += r1.x; v3 += r1.y;
            }
            if (EPI == 2){
                v0 = to_tf32(gelu_tanh(v0)); v1 = to_tf32(gelu_tanh(v1));
                v2 = to_tf32(gelu_tanh(v2)); v3 = to_tf32(gelu_tanh(v3));
            }
            float2 w0; w0.x = v0; w0.y = v1;
            float2 w1; w1.x = v2; w1.y = v3;
            *(float2*)(C_ + (size_t)row*N + col)     = w0;
            *(float2*)(C_ + (size_t)(row+8)*N + col) = w1;
        }
    }
}

// ---------------- weight transpose (tf32-rounded): WT[n][k] = W[k][n] ----------------
__global__ void transpose_kernel(const float* __restrict__ W, float* __restrict__ WT,
                                 int K, int N){
    __shared__ float t[32][33];
    int n0 = blockIdx.x*32, k0 = blockIdx.y*32;
    int tx = threadIdx.x, ty = threadIdx.y;     // 32 x 8
#pragma unroll
    for (int i=0;i<32;i+=8)
        t[ty+i][tx] = W[(size_t)(k0+ty+i)*N + n0+tx];
    __syncthreads();
#pragma unroll
    for (int i=0;i<32;i+=8)
        WT[(size_t)(n0+ty+i)*K + k0+tx] = to_tf32(t[tx][ty+i]);
}

// ---------------- LayerNorm (tf32-rounded output): one warp per row of 384 ----------------
__global__ void __launch_bounds__(256) ln_kernel(const float* __restrict__ in,
        float* __restrict__ out, const float* __restrict__ g,
        const float* __restrict__ b, float eps){
    int warp = threadIdx.x >> 5, lane = threadIdx.x & 31;
    int row  = blockIdx.x * 8 + warp;
    const float4* ip = (const float4*)(in + (size_t)row*CCD);
    float4 v[3];
    float s = 0.f, ss = 0.f;
#pragma unroll
    for (int j=0;j<3;j++){
        v[j] = ip[lane + j*32];
        s  += v[j].x + v[j].y + v[j].z + v[j].w;
        ss += v[j].x*v[j].x + v[j].y*v[j].y + v[j].z*v[j].z + v[j].w*v[j].w;
    }
#pragma unroll
    for (int o=16;o;o>>=1){
        s  += __shfl_xor_sync(0xffffffffu, s,  o);
        ss += __shfl_xor_sync(0xffffffffu, ss, o);
    }
    float mean = s * (1.f/CCD);
    float var  = ss * (1.f/CCD) - mean*mean;
    float r    = rsqrtf(var + eps);
    float4* op = (float4*)(out + (size_t)row*CCD);
    if (g){
#pragma unroll
        for (int j=0;j<3;j++){
            float4 gg = ((const float4*)g)[lane + j*32];
            float4 bb = ((const float4*)b)[lane + j*32];
            float4 y;
            y.x = to_tf32((v[j].x-mean)*r*gg.x + bb.x);
            y.y = to_tf32((v[j].y-mean)*r*gg.y + bb.y);
            y.z = to_tf32((v[j].z-mean)*r*gg.z + bb.z);
            y.w = to_tf32((v[j].w-mean)*r*gg.w + bb.w);
            op[lane + j*32] = y;
        }
    } else {
#pragma unroll
        for (int j=0;j<3;j++){
            float4 y;
            y.x = to_tf32((v[j].x-mean)*r); y.y = to_tf32((v[j].y-mean)*r);
            y.z = to_tf32((v[j].z-mean)*r); y.w = to_tf32((v[j].w-mean)*r);
            op[lane + j*32] = y;
        }
    }
}

// ---------------- mask dtype classification + conversion ----------------
__global__ void mask_conv(const unsigned char* __restrict__ m, float* __restrict__ out){
    __shared__ int cls1, cls3;
    if (threadIdx.x == 0){ cls1 = 0; cls3 = 0; }
    __syncthreads();
    int a1 = 0, a3 = 0;
    for (int i = threadIdx.x; i < MROWS; i += blockDim.x){
        if (m[i]){
            int ph = i & 3;
            if (ph == 1) a1 = 1;
            if (ph == 3) a3 = 1;
        }
    }
    if (a1) atomicOr(&cls1, 1);
    if (a3) atomicOr(&cls3, 1);
    __syncthreads();
    bool isb8  = (cls1 != 0);
    bool isf32 = (!isb8) && (cls3 != 0);
    for (int i = threadIdx.x; i < MROWS; i += blockDim.x){
        float v;
        if (isb8)       v = m[i] ? 1.f : 0.f;
        else if (isf32) v = (((const float*)m)[i] != 0.f) ? 1.f : 0.f;
        else            v = (((const int*)m)[i]   != 0  ) ? 1.f : 0.f;
        out[i] = v;
    }
}

// ---------------- fused attention (O output tf32-rounded) ----------------
#define ATTN_SMEM_FLOATS (64*52 + 128*52 + 128*56 + 64*132 + 4*64)

__global__ void __launch_bounds__(256) attn_kernel(const float* __restrict__ Q,
        const float* __restrict__ KV, const float* __restrict__ maskf,
        float* __restrict__ O){
    extern __shared__ float smn[];
    float (*Qs)[52]  = (float(*)[52]) (smn);
    float (*Ks)[52]  = (float(*)[52]) (smn + 64*52);
    float (*Vs)[56]  = (float(*)[56]) (smn + 64*52 + 128*52);
    float (*Ss)[132] = (float(*)[132])(smn + 64*52 + 128*52 + 128*56);
    float* m_s  = smn + 64*52 + 128*52 + 128*56 + 64*132;
    float* l_s  = m_s  + 64;
    float* sc_s = l_s  + 64;
    float* mk_s = sc_s + 64;

    const int b = blockIdx.y, h = blockIdx.x;
    const int tid = threadIdx.x, lane = tid & 31, wid = tid >> 5;
    const int l4 = lane & 3, ld4 = lane >> 2;
    const int wm = wid >> 1, wn = wid & 1;
    const int mr = wm*16 + ld4;
    const int srow = tid >> 2, sub = tid & 3;

    const float* qh = Q  + ((size_t)b*NQC)*CCD + h*DHC;
    const float* kh = KV + ((size_t)b*NCC)*(2*CCD) + h*DHC;
    const float* vh = kh + CCD;
    const float scale = 0.14433756729740643f;

    for (int i = tid; i < 64*48; i += 256){
        int r = i/48, c = i - r*48;
        Qs[r][c] = to_tf32(qh[(size_t)r*CCD + c] * scale);
    }
    if (tid < 64){
        m_s[tid] = -1e30f; l_s[tid] = 0.f;
        mk_s[tid] = maskf[b*NQC + tid];
    }
    float oacc[3][4];
#pragma unroll
    for (int ni=0;ni<3;ni++)
#pragma unroll
        for (int j=0;j<4;j++) oacc[ni][j] = 0.f;
    __syncthreads();

    for (int c0 = 0; c0 < NCC; c0 += 128){
        for (int i = tid; i < 128*48; i += 256){
            int r = i/48, c = i - r*48;
            Ks[r][c] = to_tf32(kh[(size_t)(c0+r)*(2*CCD) + c]);
            Vs[r][c] = to_tf32(vh[(size_t)(c0+r)*(2*CCD) + c]);
        }
        __syncthreads();

        float sacc[8][4];
#pragma unroll
        for (int ni=0;ni<8;ni++){ sacc[ni][0]=sacc[ni][1]=sacc[ni][2]=sacc[ni][3]=0.f; }
#pragma unroll
        for (int k=0;k<48;k+=8){
            float a0=Qs[mr][k+l4], a1=Qs[mr+8][k+l4];
            float a2=Qs[mr][k+l4+4], a3=Qs[mr+8][k+l4+4];
#pragma unroll
            for (int ni=0;ni<8;ni++){
                int nn = wn*64 + ni*8 + ld4;
                mma8(sacc[ni], a0,a1,a2,a3, Ks[nn][k+l4], Ks[nn][k+l4+4]);
            }
        }
#pragma unroll
        for (int ni=0;ni<8;ni++){
            int cc = wn*64 + ni*8 + 2*l4;
            Ss[mr  ][cc] = sacc[ni][0]; Ss[mr  ][cc+1] = sacc[ni][1];
            Ss[mr+8][cc] = sacc[ni][2]; Ss[mr+8][cc+1] = sacc[ni][3];
        }
        __syncthreads();

        {
            float keep = mk_s[srow];
            float mold = m_s[srow];
            float mx = -1e30f;
#pragma unroll 8
            for (int j=0;j<32;j++){
                float s = Ss[srow][sub*32 + j] * keep;
                mx = fmaxf(mx, s);
            }
            mx = fmaxf(mx, __shfl_xor_sync(0xffffffffu, mx, 1));
            mx = fmaxf(mx, __shfl_xor_sync(0xffffffffu, mx, 2));
            float mnew = fmaxf(mold, mx);
            float lsum = 0.f;
#pragma unroll 8
            for (int j=0;j<32;j++){
                int cc = sub*32 + j;
                float s = Ss[srow][cc] * keep;
                float p = __expf(s - mnew);
                lsum += p;
                Ss[srow][cc] = to_tf32(p);
            }
            lsum += __shfl_xor_sync(0xffffffffu, lsum, 1);
            lsum += __shfl_xor_sync(0xffffffffu, lsum, 2);
            if (sub == 0){
                float scl = __expf(mold - mnew);
                m_s[srow] = mnew;
                l_s[srow] = l_s[srow]*scl + lsum;
                sc_s[srow] = scl;
            }
        }
        __syncthreads();

        {
            float s0 = sc_s[mr], s1 = sc_s[mr+8];
#pragma unroll
            for (int ni=0;ni<3;ni++){
                oacc[ni][0]*=s0; oacc[ni][1]*=s0; oacc[ni][2]*=s1; oacc[ni][3]*=s1;
            }
#pragma unroll
            for (int k=0;k<128;k+=8){
                float a0=Ss[mr][k+l4], a1=Ss[mr+8][k+l4];
                float a2=Ss[mr][k+l4+4], a3=Ss[mr+8][k+l4+4];
#pragma unroll
                for (int ni=0;ni<3;ni++){
                    int nn = wn*24 + ni*8 + ld4;
                    mma8(oacc[ni], a0,a1,a2,a3, Vs[k+l4][nn], Vs[k+l4+4][nn]);
                }
            }
        }
        __syncthreads();
    }

    float inv0 = 1.f / l_s[mr];
    float inv1 = 1.f / l_s[mr+8];
#pragma unroll
    for (int ni=0;ni<3;ni++){
        int cc = wn*24 + ni*8 + 2*l4;
        size_t b0 = ((size_t)b*NQC + mr  )*CCD + h*DHC + cc;
        size_t b1 = ((size_t)b*NQC + mr+8)*CCD + h*DHC + cc;
        O[b0] = to_tf32(oacc[ni][0]*inv0); O[b0+1] = to_tf32(oacc[ni][1]*inv0);
        O[b1] = to_tf32(oacc[ni][2]*inv1); O[b1+1] = to_tf32(oacc[ni][3]*inv1);
    }
}

// ---------------- launcher ----------------
static float* sym_addr(const void* sym){
    void* p = nullptr;
    cudaGetSymbolAddress(&p, sym);
    return (float*)p;
}

extern "C" void kernel_launch(void* const* d_in, const int* in_sizes, int n_in,
                              void* d_out, int out_size){
    const float* x    = (const float*)d_in[0];
    const float* ctx  = (const float*)d_in[1];
    const unsigned char* mask = (const unsigned char*)d_in[2];
    const float* Wq   = (const float*)d_in[3];
    const float* bq   = (const float*)d_in[4];
    const float* Wkv  = (const float*)d_in[5];
    const float* bkv  = (const float*)d_in[6];
    const float* Wo   = (const float*)d_in[7];
    const float* bo   = (const float*)d_in[8];
    const float* gctx = (const float*)d_in[9];
    const float* bctx = (const float*)d_in[10];
    const float* W1   = (const float*)d_in[11];
    const float* b1   = (const float*)d_in[12];
    const float* W2   = (const float*)d_in[13];
    const float* b2   = (const float*)d_in[14];
    float* out = (float*)d_out;

    float* xn = sym_addr(g_xn);
    float* cn = sym_addr(g_cn);
    float* qb = sym_addr(g_q);
    float* kv = sym_addr(g_kv);
    float* ob = sym_addr(g_ob);
    float* x1 = sym_addr(g_x1);
    float* hb = sym_addr(g_h);
    float* mk = sym_addr(g_mk);
    float* wt = sym_addr(g_wt);

    float* WqT  = wt;                      // 384x384
    float* WkvT = wt + 147456;             // 768x384
    float* WoT  = wt + 442368;             // 384x384
    float* W1T  = wt + 589824;             // 1536x384
    float* W2T  = wt + 1179648;            // 384x1536

    const int smem_attn = ATTN_SMEM_FLOATS * 4;
    cudaFuncSetAttribute(attn_kernel, cudaFuncAttributeMaxDynamicSharedMemorySize, smem_attn);
    cudaFuncSetAttribute(gemm_cp<0>, cudaFuncAttributeMaxDynamicSharedMemorySize, GEMM_SMEM);
    cudaFuncSetAttribute(gemm_cp<1>, cudaFuncAttributeMaxDynamicSharedMemorySize, GEMM_SMEM);
    cudaFuncSetAttribute(gemm_cp<2>, cudaFuncAttributeMaxDynamicSharedMemorySize, GEMM_SMEM);

    dim3 tb(32, 8);
    transpose_kernel<<<dim3(CCD/32,  CCD/32 ), tb>>>(Wq,  WqT,  CCD,  CCD);
    transpose_kernel<<<dim3(2*CCD/32,CCD/32 ), tb>>>(Wkv, WkvT, CCD,  2*CCD);
    transpose_kernel<<<dim3(CCD/32,  CCD/32 ), tb>>>(Wo,  WoT,  CCD,  CCD);
    transpose_kernel<<<dim3(HIDC/32, CCD/32 ), tb>>>(W1,  W1T,  CCD,  HIDC);
    transpose_kernel<<<dim3(CCD/32,  HIDC/32), tb>>>(W2,  W2T,  HIDC, CCD);

    // 1. LN(x), LN(context), mask conversion
    ln_kernel<<<MROWS/8, 256>>>(x, xn, nullptr, nullptr, 1e-6f);
    ln_kernel<<<CROWS/8, 256>>>(ctx, cn, gctx, bctx, 1e-5f);
    mask_conv<<<1, 256>>>(mask, mk);

    // 2. q = xn@Wq + bq ; kv = cn@Wkv + bkv
    gemm_cp<0><<<dim3(CCD/128,   MROWS/128), 128, GEMM_SMEM>>>(xn, WqT,  bq,  nullptr, qb, MROWS, CCD,   CCD);
    gemm_cp<0><<<dim3(2*CCD/128, CROWS/128), 128, GEMM_SMEM>>>(cn, WkvT, bkv, nullptr, kv, CROWS, 2*CCD, CCD);

    // 3. attention
    attn_kernel<<<dim3(HCN, BTC), 256, smem_attn>>>(qb, kv, mk, ob);

    // 4. x1 = x + o@Wo + bo
    gemm_cp<1><<<dim3(CCD/128, MROWS/128), 128, GEMM_SMEM>>>(ob, WoT, bo, x, x1, MROWS, CCD, CCD);

    // 5. MLP: out = x1 + gelu(LN(x1)@W1+b1)@W2 + b2
    ln_kernel<<<MROWS/8, 256>>>(x1, xn, nullptr, nullptr, 1e-6f);
    gemm_cp<2><<<dim3(HIDC/128, MROWS/128), 128, GEMM_SMEM>>>(xn, W1T, b1, nullptr, hb, MROWS, HIDC, CCD);
    gemm_cp<1><<<dim3(CCD/128,  MROWS/128), 128, GEMM_SMEM>>>(hb, W2T, b2, x1, out, MROWS, CCD, HIDC);
}